// round 10
// baseline (speedup 1.0000x reference)
#include <cuda_runtime.h>
#include <cstdint>

// Problem shapes (fixed)
#define B_ 256
#define R_ 64
#define F_ 2048
#define H_ 512
#define D_ 512
#define MROWS (B_*R_)      // 16384 rows of the big GEMM

// GEMM tiling
#define KT 32              // K tile
#define MT 128             // M tile (2 batches)
#define NT 128             // N tile (4 n-chunks cover DIM=512)
#define NKT (F_/KT)        // 64 K iterations
#define NSTAGE 3

// smem per stage: A [128 rows][36 words] (144B stride), B [128 n][36 words]
// 144B stride: consecutive rows offset by 4 banks -> 8 rows cover all 32 banks
// (conflict-free for both 16B STS chunks and ldmatrix row reads)
#define A_STAGE_BYTES (128*144)             // 18432
#define B_STAGE_BYTES (128*144)             // 18432
#define AS_BYTES (NSTAGE*A_STAGE_BYTES)     // 55296
#define BS_BYTES (NSTAGE*B_STAGE_BYTES)     // 55296
#define SMEM_BYTES (AS_BYTES + BS_BYTES)    // 110592  (x2 CTAs = 216KB < 228KB)

// Scratch (device globals: no allocations allowed)
__device__ float    g_p[B_ * D_];          // prev @ W2 + b2
__device__ float    g_score[4 * MROWS];    // partial scores, one slab per n-chunk
__device__ uint32_t g_WwT[D_ * F_];        // W_w transposed [D][F], tf32-rounded bits

// ---------------------------------------------------------------------------
// helpers
// ---------------------------------------------------------------------------
__device__ __forceinline__ void cp16(uint32_t dst, const void* src) {
    asm volatile("cp.async.cg.shared.global [%0], [%1], 16;" :: "r"(dst), "l"(src));
}
__device__ __forceinline__ uint32_t smem_u32(const void* p) {
    uint32_t a;
    asm("{ .reg .u64 t; cvta.to.shared.u64 t, %1; cvt.u32.u64 %0, t; }"
        : "=r"(a) : "l"(p));
    return a;
}
__device__ __forceinline__ void cp_commit() { asm volatile("cp.async.commit_group;"); }
__device__ __forceinline__ void cp_wait1()  { asm volatile("cp.async.wait_group 1;"); }
__device__ __forceinline__ void cp_wait0()  { asm volatile("cp.async.wait_group 0;"); }

__device__ __forceinline__ void ldsm_x4(uint32_t* r, uint32_t addr) {
    asm volatile("ldmatrix.sync.aligned.m8n8.x4.shared.b16 {%0,%1,%2,%3}, [%4];"
                 : "=r"(r[0]), "=r"(r[1]), "=r"(r[2]), "=r"(r[3]) : "r"(addr));
}

__device__ __forceinline__ void mma_tf32(float* d, const uint32_t* a,
                                         uint32_t b0, uint32_t b1) {
    asm volatile(
        "mma.sync.aligned.m16n8k8.row.col.f32.tf32.tf32.f32 "
        "{%0,%1,%2,%3}, {%4,%5,%6,%7}, {%8,%9}, {%0,%1,%2,%3};\n"
        : "+f"(d[0]), "+f"(d[1]), "+f"(d[2]), "+f"(d[3])
        : "r"(a[0]), "r"(a[1]), "r"(a[2]), "r"(a[3]), "r"(b0), "r"(b1));
}

// ---------------------------------------------------------------------------
// Kernel 0: transpose W_w -> g_WwT [D][F], tf32-rounded (rna) bits
// grid (64, 16), block (32,8)
// ---------------------------------------------------------------------------
__global__ void __launch_bounds__(256) transpose_ww_kernel(const float* __restrict__ Ww) {
    __shared__ float t[32][33];
    const int f0 = blockIdx.x * 32;
    const int d0 = blockIdx.y * 32;
    const int tx = threadIdx.x, ty = threadIdx.y;
    #pragma unroll
    for (int i = ty; i < 32; i += 8)
        t[i][tx] = Ww[(size_t)(f0 + i) * D_ + d0 + tx];
    __syncthreads();
    #pragma unroll
    for (int r = ty; r < 32; r += 8) {
        uint32_t bits;
        asm("cvt.rna.tf32.f32 %0, %1;" : "=r"(bits) : "f"(t[tx][r]));
        g_WwT[(size_t)(d0 + r) * F_ + f0 + tx] = bits;
    }
}

// ---------------------------------------------------------------------------
// Kernel 1: p[b,d] = prev[b,:] @ W2[:,d] + W2b[d]
// grid 32, block 512 (4 warps/SMSP); ps broadcasts vectorized as float4
// ---------------------------------------------------------------------------
__global__ void __launch_bounds__(512) prep_p_kernel(
        const float* __restrict__ prev,
        const float* __restrict__ W2w,
        const float* __restrict__ W2b) {
    __shared__ float4 ps4[8 * 128];   // 8 batches x 512 floats
    const int bg = blockIdx.x;
    const int tid = threadIdx.x;      // = d

    const float4* pv = (const float4*)(prev + (size_t)bg * 8 * 512);
    for (int i = tid; i < 1024; i += 512) ps4[i] = pv[i];
    __syncthreads();

    const int d = tid;
    const float bias = W2b[d];
    float acc[8];
    #pragma unroll
    for (int i = 0; i < 8; i++) acc[i] = bias;

    for (int h = 0; h < 512; h += 4) {
        float w[4];
        #pragma unroll
        for (int j = 0; j < 4; j++) w[j] = W2w[(h + j) * 512 + d];
        #pragma unroll
        for (int i = 0; i < 8; i++) {
            const float4 p = ps4[i * 128 + (h >> 2)];
            acc[i] = fmaf(p.x, w[0], acc[i]);
            acc[i] = fmaf(p.y, w[1], acc[i]);
            acc[i] = fmaf(p.z, w[2], acc[i]);
            acc[i] = fmaf(p.w, w[3], acc[i]);
        }
    }
    #pragma unroll
    for (int i = 0; i < 8; i++) g_p[(bg * 8 + i) * 512 + d] = acc[i];
}

// ---------------------------------------------------------------------------
// ncu-steering no-op (makes the gemm the 4th kernel launch -> profiled slot 6)
// ---------------------------------------------------------------------------
__global__ void steer_kernel() {}

// ---------------------------------------------------------------------------
// Kernel 2: per CTA, C[128,128] = feat_rows @ W_w[:, n-chunk] (tf32 mma.sync),
// fragments via ldmatrix.x4; then score partials.
// grid (4 n-chunks, 128 m-tiles), 256 threads, 2 CTAs/SM, 3-stage cp.async.
// ---------------------------------------------------------------------------
__global__ void __launch_bounds__(256, 2) gemm_score_kernel(
        const float* __restrict__ features,
        const float* __restrict__ Wb,
        const float* __restrict__ W3) {
    extern __shared__ uint4 smem[];
    const uint32_t sbase = smem_u32(smem);
    const uint32_t sA = sbase;
    const uint32_t sB = sbase + AS_BYTES;

    const int tid  = threadIdx.x;
    const int wid  = tid >> 5;
    const int lane = tid & 31;
    const int tig  = lane & 3;        // k within frag (epilogue indexing)
    const int gid  = lane >> 2;       // row within frag (epilogue indexing)
    const int wm   = wid & 3;         // warp m position (4 x 32 rows)
    const int wn   = wid >> 2;        // warp n position (2 x 64 cols)
    const int n0   = blockIdx.x * NT; // n-chunk (fast dim -> co-resident share A)
    const int m0   = blockIdx.y * MT;

    const float* gA = features + (size_t)m0 * F_;

    float acc[2][8][4];
    #pragma unroll
    for (int i = 0; i < 2; i++)
        #pragma unroll
        for (int j = 0; j < 8; j++)
            #pragma unroll
            for (int k = 0; k < 4; k++) acc[i][j][k] = 0.f;

    // --- async tile load: A 128x32 floats, B(n-major) 128x32 tf32-bits ---
    auto load_tile = [&](int kt, int buf) {
        const float* a = gA + kt * KT;
        const uint32_t dstA = sA + buf * A_STAGE_BYTES;
        #pragma unroll
        for (int t = 0; t < 4; t++) {
            const int i = tid + t * 256;          // 1024 chunks
            const int row = i >> 3, c = i & 7;
            cp16(dstA + (uint32_t)(row * 144 + c * 16),
                 a + (size_t)row * F_ + c * 4);
        }
        const uint32_t* b = g_WwT + (size_t)n0 * F_ + kt * KT;
        const uint32_t dstB = sB + buf * B_STAGE_BYTES;
        #pragma unroll
        for (int t = 0; t < 4; t++) {
            const int i = tid + t * 256;          // 1024 chunks
            const int row = i >> 3, c = i & 7;    // row = n (0..127), c = k-chunk
            cp16(dstB + (uint32_t)(row * 144 + c * 16),
                 b + (size_t)row * F_ + c * 4);
        }
        cp_commit();
    };

    load_tile(0, 0);
    load_tile(1, 1);

    // per-lane ldmatrix base offsets (row = +(lane&15), k-half = lane>>4)
    const uint32_t lrow  = (uint32_t)(lane & 15);
    const uint32_t lkoff = (uint32_t)(lane >> 4) * 16;
    const uint32_t offA  = (uint32_t)(wm * 32 + lrow) * 144 + lkoff;   // + mf*16*144
    const uint32_t offB  = (uint32_t)(wn * 64 + lrow) * 144 + lkoff;   // + j*16*144

    int buf = 0;
    for (int kt = 0; kt < NKT; kt++) {
        if (kt + 1 < NKT) cp_wait1(); else cp_wait0();
        __syncthreads();          // tile kt visible; buffer (kt+2)%3 fully consumed

        // refill issued BEFORE compute: overlaps with this iteration's mma.
        if (kt + 2 < NKT) load_tile(kt + 2, (buf + 2 >= NSTAGE) ? buf + 2 - NSTAGE : buf + 2);

        const uint32_t aBase = sA + buf * A_STAGE_BYTES + offA;
        const uint32_t bBase = sB + buf * B_STAGE_BYTES + offB;
        #pragma unroll
        for (int k8 = 0; k8 < 4; k8++) {
            const uint32_t kOff = (uint32_t)k8 * 32;
            uint32_t a0[4], a1[4];
            ldsm_x4(a0, aBase + kOff);                 // rows wm*32+0..15
            ldsm_x4(a1, aBase + 16 * 144 + kOff);      // rows wm*32+16..31
            #pragma unroll
            for (int j = 0; j < 4; j++) {              // nf = 2j, 2j+1
                uint32_t rb[4];
                ldsm_x4(rb, bBase + (uint32_t)j * (16 * 144) + kOff);
                // rb[0]=b0(nf=2j), rb[1]=b0(nf=2j+1), rb[2]=b1(2j), rb[3]=b1(2j+1)
                mma_tf32(acc[0][2*j],   a0, rb[0], rb[2]);
                mma_tf32(acc[1][2*j],   a1, rb[0], rb[2]);
                mma_tf32(acc[0][2*j+1], a0, rb[1], rb[3]);
                mma_tf32(acc[1][2*j+1], a1, rb[1], rb[3]);
            }
        }

        buf = (buf == NSTAGE - 1) ? 0 : buf + 1;
    }

    // -------- epilogue: score partials --------
    float part[4] = {0.f, 0.f, 0.f, 0.f};
    {
        // each warp's 32 rows lie inside one batch (wm*32 block within 64-row batch)
        const int b = (m0 + wm * 32) >> 6;
        const float* pB  = g_p + b * 512 + n0 + wn * 64;
        const float* w3B = W3 + n0 + wn * 64;
        const float* wbB = Wb + n0 + wn * 64;
        #pragma unroll
        for (int nf = 0; nf < 8; nf++) {
            #pragma unroll
            for (int c = 0; c < 2; c++) {
                const int dl = nf * 8 + 2 * tig + c;
                const float add = wbB[dl] + pB[dl];
                const float w3  = w3B[dl];
                float t0, t1, t2, t3;
                asm("tanh.approx.f32 %0, %1;" : "=f"(t0) : "f"(acc[0][nf][c]     + add));
                asm("tanh.approx.f32 %0, %1;" : "=f"(t1) : "f"(acc[0][nf][2 + c] + add));
                asm("tanh.approx.f32 %0, %1;" : "=f"(t2) : "f"(acc[1][nf][c]     + add));
                asm("tanh.approx.f32 %0, %1;" : "=f"(t3) : "f"(acc[1][nf][2 + c] + add));
                part[0] = fmaf(w3, t0, part[0]);   // row gid
                part[1] = fmaf(w3, t1, part[1]);   // row gid+8
                part[2] = fmaf(w3, t2, part[2]);   // row gid+16
                part[3] = fmaf(w3, t3, part[3]);   // row gid+24
            }
        }
    }
    // reduce over tig (lanes differing in bits 0..1 hold different d's)
    #pragma unroll
    for (int msk = 1; msk < 4; msk <<= 1) {
        #pragma unroll
        for (int i = 0; i < 4; i++)
            part[i] += __shfl_xor_sync(0xffffffffu, part[i], msk);
    }

    __syncthreads();                 // done with tile smem; repurpose
    float* scoreS = (float*)smem;    // [2][128]
    if (tig == 0) {
        const int rb = wm * 32 + gid;
        scoreS[wn * 128 + rb]      = part[0];
        scoreS[wn * 128 + rb + 8]  = part[1];
        scoreS[wn * 128 + rb + 16] = part[2];
        scoreS[wn * 128 + rb + 24] = part[3];
    }
    __syncthreads();
    if (tid < 128) {
        g_score[blockIdx.x * MROWS + m0 + tid] = scoreS[tid] + scoreS[128 + tid];
    }
}

// ---------------------------------------------------------------------------
// Kernel 3: softmax over 64 scores + weighted feature sum.
// grid (2 column-halves, 256 batches), 256 threads; r-loop unroll 8 for MLP.
// ---------------------------------------------------------------------------
__global__ void __launch_bounds__(256) softmax_q_kernel(
        const float* __restrict__ features,
        float* __restrict__ out) {
    __shared__ float s_s[64];
    __shared__ float aw_s[64];
    const int half = blockIdx.x;     // 0 or 1 (256 float4 columns each)
    const int b    = blockIdx.y;
    const int tid  = threadIdx.x;

    if (tid < 64) {
        float v = 0.f;
        #pragma unroll
        for (int p = 0; p < 4; p++) v += g_score[p * MROWS + b * 64 + tid];
        s_s[tid] = v;
    }
    __syncthreads();

    // every thread computes identical max/sum (deterministic, smem broadcast)
    float m = -1e30f;
    #pragma unroll 8
    for (int i = 0; i < 64; i++) m = fmaxf(m, s_s[i]);
    float sum = 0.f;
    #pragma unroll 8
    for (int i = 0; i < 64; i++) sum += expf(s_s[i] - m);

    if (tid < 64) aw_s[tid] = expf(s_s[tid] - m) / sum;
    __syncthreads();

    const int col = half * 256 + tid;          // float4 column index (0..511)
    const float4* f4 = (const float4*)(features + (size_t)b * R_ * F_) + col;
    float4 a0 = {0.f, 0.f, 0.f, 0.f};
    #pragma unroll
    for (int r = 0; r < 64; r += 8) {
        float4 x[8];
        float  w[8];
        #pragma unroll
        for (int j = 0; j < 8; j++) { x[j] = f4[(size_t)(r + j) * 512]; w[j] = aw_s[r + j]; }
        #pragma unroll
        for (int j = 0; j < 8; j++) {
            a0.x = fmaf(w[j], x[j].x, a0.x); a0.y = fmaf(w[j], x[j].y, a0.y);
            a0.z = fmaf(w[j], x[j].z, a0.z); a0.w = fmaf(w[j], x[j].w, a0.w);
        }
    }
    ((float4*)out)[(size_t)b * 512 + col] = a0;
}

// ---------------------------------------------------------------------------
// kernel_launch
// inputs: 0 features, 1 prev, 2 W_w, 3 W_b, 4 W2_w, 5 W2_b, 6 W3_w, 7 W3_b
// (W3_b unused: softmax is shift-invariant)
// ---------------------------------------------------------------------------
extern "C" void kernel_launch(void* const* d_in, const int* in_sizes, int n_in,
                              void* d_out, int out_size) {
    const float* features = (const float*)d_in[0];
    const float* prev     = (const float*)d_in[1];
    const float* Ww       = (const float*)d_in[2];
    const float* Wb       = (const float*)d_in[3];
    const float* W2w      = (const float*)d_in[4];
    const float* W2b      = (const float*)d_in[5];
    const float* W3w      = (const float*)d_in[6];
    float* out = (float*)d_out;

    cudaFuncSetAttribute(gemm_score_kernel,
                         cudaFuncAttributeMaxDynamicSharedMemorySize, SMEM_BYTES);

    transpose_ww_kernel<<<dim3(64, 16), dim3(32, 8)>>>(Ww);
    prep_p_kernel<<<32, 512>>>(prev, W2w, W2b);
    steer_kernel<<<1, 1>>>();   // aligns gemm with ncu's -s 5 -c 1 capture slot
    gemm_score_kernel<<<dim3(4, 128), 256, SMEM_BYTES>>>(features, Wb, W3w);
    softmax_q_kernel<<<dim3(2, B_), 256>>>(features, out);
}

// round 12
// speedup vs baseline: 1.0423x; 1.0423x over previous
#include <cuda_runtime.h>
#include <cstdint>

// Problem shapes (fixed)
#define B_ 256
#define R_ 64
#define F_ 2048
#define H_ 512
#define D_ 512
#define MROWS (B_*R_)      // 16384 rows of the big GEMM

// GEMM tiling
#define KT 32              // K tile
#define MT 128             // M tile (2 batches)
#define NT 128             // N tile (4 n-chunks cover DIM=512)
#define NKT (F_/KT)        // 64 K iterations
#define NSTAGE 3

// smem: per stage A [128][9] uint4 (18432B), B [32][34] uint4 (17408B)
// B row stride 136 words: 136 mod 32 = 8 -> bank = 8*tig+gid (perfect perm)
#define AS_STAGE_U4 (128*9)                 // 1152
#define BS_STAGE_U4 (32*34)                 // 1088
#define AS_BYTES (NSTAGE*AS_STAGE_U4*16)    // 55296
#define BS_BYTES (NSTAGE*BS_STAGE_U4*16)    // 52224
#define SMEM_BYTES (AS_BYTES + BS_BYTES)    // 107520  (x2 CTAs = 215KB < 228KB)

// Scratch (device globals: no allocations allowed)
__device__ float    g_p[B_ * D_];          // prev @ W2 + b2
__device__ float    g_score[4 * MROWS];    // partial scores, one slab per n-chunk
__device__ uint32_t g_WwB[F_ * D_];        // W_w pre-rounded to tf32 (rna), same layout

// ---------------------------------------------------------------------------
// helpers
// ---------------------------------------------------------------------------
__device__ __forceinline__ void cp16(uint32_t dst, const void* src) {
    asm volatile("cp.async.cg.shared.global [%0], [%1], 16;" :: "r"(dst), "l"(src));
}
__device__ __forceinline__ uint32_t smem_u32(const void* p) {
    uint32_t a;
    asm("{ .reg .u64 t; cvta.to.shared.u64 t, %1; cvt.u32.u64 %0, t; }"
        : "=r"(a) : "l"(p));
    return a;
}
__device__ __forceinline__ void cp_commit() { asm volatile("cp.async.commit_group;"); }
__device__ __forceinline__ void cp_wait1()  { asm volatile("cp.async.wait_group 1;"); }
__device__ __forceinline__ void cp_wait0()  { asm volatile("cp.async.wait_group 0;"); }

__device__ __forceinline__ void mma_tf32(float* d, const uint32_t* a,
                                         uint32_t b0, uint32_t b1) {
    asm volatile(
        "mma.sync.aligned.m16n8k8.row.col.f32.tf32.tf32.f32 "
        "{%0,%1,%2,%3}, {%4,%5,%6,%7}, {%8,%9}, {%0,%1,%2,%3};\n"
        : "+f"(d[0]), "+f"(d[1]), "+f"(d[2]), "+f"(d[3])
        : "r"(a[0]), "r"(a[1]), "r"(a[2]), "r"(a[3]), "r"(b0), "r"(b1));
}

// ---------------------------------------------------------------------------
// Kernel 0: pre-round W_w to tf32 (rna) bits, same [F, D] layout
// ---------------------------------------------------------------------------
__global__ void __launch_bounds__(256) cvt_ww_kernel(const float* __restrict__ Ww) {
    const int i = blockIdx.x * 256 + threadIdx.x;      // uint4 index
    const float4 v = ((const float4*)Ww)[i];
    uint4 t;
    asm("cvt.rna.tf32.f32 %0, %1;" : "=r"(t.x) : "f"(v.x));
    asm("cvt.rna.tf32.f32 %0, %1;" : "=r"(t.y) : "f"(v.y));
    asm("cvt.rna.tf32.f32 %0, %1;" : "=r"(t.z) : "f"(v.z));
    asm("cvt.rna.tf32.f32 %0, %1;" : "=r"(t.w) : "f"(v.w));
    ((uint4*)g_WwB)[i] = t;
}

// ---------------------------------------------------------------------------
// Kernel 1: p[b,d] = prev[b,:] @ W2[:,d] + W2b[d]
// grid 32, block 512; h-loop unrolled x8 (W2w MLP 8), ps as float4 broadcasts
// ---------------------------------------------------------------------------
__global__ void __launch_bounds__(512) prep_p_kernel(
        const float* __restrict__ prev,
        const float* __restrict__ W2w,
        const float* __restrict__ W2b) {
    __shared__ float4 ps4[8 * 128];   // 8 batches x 512 floats
    const int bg = blockIdx.x;
    const int tid = threadIdx.x;      // = d

    const float4* pv = (const float4*)(prev + (size_t)bg * 8 * 512);
    for (int i = tid; i < 1024; i += 512) ps4[i] = pv[i];
    __syncthreads();

    const int d = tid;
    const float bias = W2b[d];
    float acc[8];
    #pragma unroll
    for (int i = 0; i < 8; i++) acc[i] = bias;

    for (int h = 0; h < 512; h += 8) {
        float w[8];
        #pragma unroll
        for (int j = 0; j < 8; j++) w[j] = W2w[(h + j) * 512 + d];
        #pragma unroll
        for (int i = 0; i < 8; i++) {
            const float4 p0 = ps4[i * 128 + (h >> 2)];
            const float4 p1 = ps4[i * 128 + (h >> 2) + 1];
            acc[i] = fmaf(p0.x, w[0], acc[i]);
            acc[i] = fmaf(p0.y, w[1], acc[i]);
            acc[i] = fmaf(p0.z, w[2], acc[i]);
            acc[i] = fmaf(p0.w, w[3], acc[i]);
            acc[i] = fmaf(p1.x, w[4], acc[i]);
            acc[i] = fmaf(p1.y, w[5], acc[i]);
            acc[i] = fmaf(p1.z, w[6], acc[i]);
            acc[i] = fmaf(p1.w, w[7], acc[i]);
        }
    }
    #pragma unroll
    for (int i = 0; i < 8; i++) g_p[(bg * 8 + i) * 512 + d] = acc[i];
}

// ---------------------------------------------------------------------------
// Kernel 2: per CTA, C[128,128] = feat_rows @ W_w[:, n-chunk] (tf32 mma.sync),
// then partial_score[row] = sum_d W3[d]*tanh(C + W_b[d] + p[b,d])
// grid (4 n-chunks, 128 m-tiles), 256 threads, 2 CTAs/SM,
// single-barrier 3-stage cp.async pipeline (refill issued before mma)
// ---------------------------------------------------------------------------
__global__ void __launch_bounds__(256, 2) gemm_score_kernel(
        const float* __restrict__ features,
        const float* __restrict__ Wb,
        const float* __restrict__ W3) {
    extern __shared__ uint4 smem[];
    uint32_t* As32 = (uint32_t*)smem;                        // [3][128][36] words
    uint32_t* Bs32 = (uint32_t*)(smem + NSTAGE*AS_STAGE_U4); // [3][32][136] words
    const uint32_t sbase = smem_u32(smem);
    const uint32_t sA = sbase;
    const uint32_t sB = sbase + AS_BYTES;

    const int tid  = threadIdx.x;
    const int wid  = tid >> 5;
    const int lane = tid & 31;
    const int gid  = lane >> 2;       // group id (row within frag)
    const int tig  = lane & 3;        // thread-in-group (k/col within frag)
    const int wm   = wid & 3;         // warp m position (4 x 32 rows)
    const int wn   = wid >> 2;        // warp n position (2 x 64 cols)
    const int n0   = blockIdx.x * NT; // n-chunk (fast dim -> co-resident share A)
    const int m0   = blockIdx.y * MT;

    const float* gA = features + (size_t)m0 * F_;
    const uint4* Bw4 = (const uint4*)g_WwB;   // row stride 128 uint4

    float acc[2][8][4];
    #pragma unroll
    for (int i = 0; i < 2; i++)
        #pragma unroll
        for (int j = 0; j < 8; j++)
            #pragma unroll
            for (int k = 0; k < 4; k++) acc[i][j][k] = 0.f;

    // --- async tile load: A 128x32 floats, B 32x128 tf32-bits ---
    auto load_tile = [&](int kt, int buf) {
        const float* a = gA + kt * KT;
        const uint32_t dstA = sA + buf * (AS_STAGE_U4 * 16);
        #pragma unroll
        for (int t = 0; t < 4; t++) {
            const int i = tid + t * 256;          // 1024 chunks
            const int row = i >> 3, c = i & 7;
            cp16(dstA + (uint32_t)(row * 144 + c * 16),
                 a + (size_t)row * F_ + c * 4);
        }
        const uint4* b = Bw4 + (size_t)(kt * 32) * 128 + (n0 >> 2);
        const uint32_t dstB = sB + buf * (BS_STAGE_U4 * 16);
        #pragma unroll
        for (int t = 0; t < 4; t++) {
            const int i = tid + t * 256;          // 1024 chunks
            const int kk = i >> 5, nq = i & 31;
            cp16(dstB + (uint32_t)(kk * 544 + nq * 16),
                 b + (size_t)kk * 128 + nq);
        }
        cp_commit();
    };

    load_tile(0, 0);
    load_tile(1, 1);

    int buf = 0;
    for (int kt = 0; kt < NKT; kt++) {
        if (kt + 1 < NKT) cp_wait1(); else cp_wait0();
        __syncthreads();          // tile kt visible; buffer (kt+2)%3 fully consumed

        // refill issued BEFORE compute: overlaps with this iteration's mma.
        if (kt + 2 < NKT) load_tile(kt + 2, (buf + 2 >= NSTAGE) ? buf + 2 - NSTAGE : buf + 2);

        const uint32_t* Ab = As32 + buf * (AS_STAGE_U4 * 4);
        const uint32_t* Bb = Bs32 + buf * (BS_STAGE_U4 * 4);
        #pragma unroll
        for (int k8 = 0; k8 < 4; k8++) {
            uint32_t a[2][4];
            const int kc = k8 * 8 + tig;
            #pragma unroll
            for (int mf = 0; mf < 2; mf++) {
                const int r0 = wm * 32 + mf * 16 + gid;
                a[mf][0] = Ab[r0 * 36 + kc];
                a[mf][1] = Ab[(r0 + 8) * 36 + kc];
                a[mf][2] = Ab[r0 * 36 + kc + 4];
                a[mf][3] = Ab[(r0 + 8) * 36 + kc + 4];
            }
            const uint32_t* Bp = Bb + (size_t)(k8 * 8 + tig) * 136 + wn * 64 + gid;
            #pragma unroll
            for (int nf = 0; nf < 8; nf++) {
                const uint32_t b0 = Bp[nf * 8];
                const uint32_t b1 = Bp[nf * 8 + 4 * 136];
                mma_tf32(acc[0][nf], a[0], b0, b1);
                mma_tf32(acc[1][nf], a[1], b0, b1);
            }
        }

        buf = (buf == NSTAGE - 1) ? 0 : buf + 1;
    }

    // -------- epilogue: score partials --------
    float part[4] = {0.f, 0.f, 0.f, 0.f};
    {
        // each warp's 32 rows lie inside one batch (wm*32 block within 64-row batch)
        const int b = (m0 + wm * 32) >> 6;
        const float* pB  = g_p + b * 512 + n0 + wn * 64;
        const float* w3B = W3 + n0 + wn * 64;
        const float* wbB = Wb + n0 + wn * 64;
        #pragma unroll
        for (int nf = 0; nf < 8; nf++) {
            #pragma unroll
            for (int c = 0; c < 2; c++) {
                const int dl = nf * 8 + 2 * tig + c;
                const float add = wbB[dl] + pB[dl];
                const float w3  = w3B[dl];
                float t0, t1, t2, t3;
                asm("tanh.approx.f32 %0, %1;" : "=f"(t0) : "f"(acc[0][nf][c]     + add));
                asm("tanh.approx.f32 %0, %1;" : "=f"(t1) : "f"(acc[0][nf][2 + c] + add));
                asm("tanh.approx.f32 %0, %1;" : "=f"(t2) : "f"(acc[1][nf][c]     + add));
                asm("tanh.approx.f32 %0, %1;" : "=f"(t3) : "f"(acc[1][nf][2 + c] + add));
                part[0] = fmaf(w3, t0, part[0]);   // row gid
                part[1] = fmaf(w3, t1, part[1]);   // row gid+8
                part[2] = fmaf(w3, t2, part[2]);   // row gid+16
                part[3] = fmaf(w3, t3, part[3]);   // row gid+24
            }
        }
    }
    // reduce over tig (lanes differing in bits 0..1 hold different d's)
    #pragma unroll
    for (int msk = 1; msk < 4; msk <<= 1) {
        #pragma unroll
        for (int i = 0; i < 4; i++)
            part[i] += __shfl_xor_sync(0xffffffffu, part[i], msk);
    }

    __syncthreads();                 // done with tile smem; repurpose
    float* scoreS = (float*)smem;    // [2][128]
    if (tig == 0) {
        const int rb = wm * 32 + gid;
        scoreS[wn * 128 + rb]      = part[0];
        scoreS[wn * 128 + rb + 8]  = part[1];
        scoreS[wn * 128 + rb + 16] = part[2];
        scoreS[wn * 128 + rb + 24] = part[3];
    }
    __syncthreads();
    if (tid < 128) {
        g_score[blockIdx.x * MROWS + m0 + tid] = scoreS[tid] + scoreS[128 + tid];
    }
}

// ---------------------------------------------------------------------------
// Kernel 3: softmax over 64 scores + weighted feature sum.
// grid (2 column-halves, 256 batches), 256 threads; r-loop unroll 16 for MLP.
// ---------------------------------------------------------------------------
__global__ void __launch_bounds__(256) softmax_q_kernel(
        const float* __restrict__ features,
        float* __restrict__ out) {
    __shared__ float s_s[64];
    __shared__ float aw_s[64];
    const int half = blockIdx.x;     // 0 or 1 (256 float4 columns each)
    const int b    = blockIdx.y;
    const int tid  = threadIdx.x;

    if (tid < 64) {
        float v = 0.f;
        #pragma unroll
        for (int p = 0; p < 4; p++) v += g_score[p * MROWS + b * 64 + tid];
        s_s[tid] = v;
    }
    __syncthreads();

    // every thread computes identical max/sum (deterministic, smem broadcast)
    float m = -1e30f;
    #pragma unroll 8
    for (int i = 0; i < 64; i++) m = fmaxf(m, s_s[i]);
    float sum = 0.f;
    #pragma unroll 8
    for (int i = 0; i < 64; i++) sum += expf(s_s[i] - m);

    if (tid < 64) aw_s[tid] = expf(s_s[tid] - m) / sum;
    __syncthreads();

    const int col = half * 256 + tid;          // float4 column index (0..511)
    const float4* f4 = (const float4*)(features + (size_t)b * R_ * F_) + col;
    float4 a0 = {0.f, 0.f, 0.f, 0.f};
    #pragma unroll
    for (int r = 0; r < 64; r += 16) {
        float4 x[16];
        float  w[16];
        #pragma unroll
        for (int j = 0; j < 16; j++) { x[j] = f4[(size_t)(r + j) * 512]; w[j] = aw_s[r + j]; }
        #pragma unroll
        for (int j = 0; j < 16; j++) {
            a0.x = fmaf(w[j], x[j].x, a0.x); a0.y = fmaf(w[j], x[j].y, a0.y);
            a0.z = fmaf(w[j], x[j].z, a0.z); a0.w = fmaf(w[j], x[j].w, a0.w);
        }
    }
    ((float4*)out)[(size_t)b * 512 + col] = a0;
}

// ---------------------------------------------------------------------------
// kernel_launch
// inputs: 0 features, 1 prev, 2 W_w, 3 W_b, 4 W2_w, 5 W2_b, 6 W3_w, 7 W3_b
// (W3_b unused: softmax is shift-invariant)
// launch order: cvt(3) prep(4) gemm(5) softmax(6) -> ncu slot 6 profiles softmax
// ---------------------------------------------------------------------------
extern "C" void kernel_launch(void* const* d_in, const int* in_sizes, int n_in,
                              void* d_out, int out_size) {
    const float* features = (const float*)d_in[0];
    const float* prev     = (const float*)d_in[1];
    const float* Ww       = (const float*)d_in[2];
    const float* Wb       = (const float*)d_in[3];
    const float* W2w      = (const float*)d_in[4];
    const float* W2b      = (const float*)d_in[5];
    const float* W3w      = (const float*)d_in[6];
    float* out = (float*)d_out;

    cudaFuncSetAttribute(gemm_score_kernel,
                         cudaFuncAttributeMaxDynamicSharedMemorySize, SMEM_BYTES);

    cvt_ww_kernel<<<(F_ * D_ / 4) / 256, 256>>>(Ww);
    prep_p_kernel<<<32, 512>>>(prev, W2w, W2b);
    gemm_score_kernel<<<dim3(4, 128), 256, SMEM_BYTES>>>(features, Wb, W3w);
    softmax_q_kernel<<<dim3(2, B_), 256>>>(features, out);
}